// round 5
// baseline (speedup 1.0000x reference)
#include <cuda_runtime.h>
#include <math.h>

#define HIDDEN     64
#define NBASIS     10
#define SEQ        96
#define BATCH      16384
#define NPAIR      (HIDDEN * NBASIS)   // 640
#define GTAB       128
#define GPTS       2                   // grid points per table block
#define ABLK       (GTAB / GPTS)       // 64 table blocks
#define PAIRS_PW   (NPAIR / 4)         // 160 pairs per warp

#define DOM_LO     (-6.0f)
#define DOM_H      (12.0f / (float)(GTAB - 4))
#define DOM_INVH   ((float)(GTAB - 4) / 12.0f)

#define TRBLK      16                  // transpose blocks (4 i-rows each)
#define XBLK       64                  // x-gather blocks

__device__ __align__(16) float g_Wct[NPAIR * HIDDEN];  // [pair][o], 160KB
__device__ float  g_xlast[BATCH];
__device__ float2 g_table[GTAB];

// ---------------------------------------------------------------------------
// Kernel P: blocks [0,16): smem-tiled transpose of Wc (4 i-rows per block)
//           blocks [16,80): gather x[:,95] -> g_xlast (coalesced later)
// ---------------------------------------------------------------------------
__global__ void __launch_bounds__(256) k_pre(const float* __restrict__ x,
                                             const float* __restrict__ Wc) {
    const int t   = threadIdx.x;
    const int bid = blockIdx.x;

    if (bid >= TRBLK) {
        int b = (bid - TRBLK) * 256 + t;
        g_xlast[b] = __ldg(x + b * SEQ + (SEQ - 1));
        return;
    }

    // transpose: this block owns i in [4*bid, 4*bid+4)  (2560 floats)
    __shared__ float s[2816];   // 2560 + pad (one pad float per 10)
    const float* src = Wc + bid * 2560;

    #pragma unroll
    for (int j = 0; j < 10; j++) {
        int gi = j * 256 + t;                    // coalesced read
        s[gi + gi / 10] = __ldg(src + gi);       // padded store, ~conflict-free
    }
    __syncthreads();

    // write g_Wct[pair][o] coalesced as float4; out f4 index q in [0,640)
    float4* dst = reinterpret_cast<float4*>(g_Wct) + bid * 640;
    #pragma unroll
    for (int j = 0; j < 3; j++) {
        int q = j * 256 + t;
        if (q < 640) {
            int pl  = q >> 4;                    // local pair  [0,40)
            int o0  = (q & 15) * 4;              // output base [0,64) step 4
            int i_l = pl / NBASIS;               // [0,4)
            int k   = pl - NBASIS * i_l;
            int base = i_l * 704 + k;            // padded smem base (704 = 640+64)
            float4 v;
            v.x = s[base + (o0 + 0) * 11];       // stride 11 = 10 + pad
            v.y = s[base + (o0 + 1) * 11];
            v.z = s[base + (o0 + 2) * 11];
            v.w = s[base + (o0 + 3) * 11];
            dst[q] = v;                          // coalesced STG.128
        }
    }
}

// ---------------------------------------------------------------------------
// Kernel A: tabulate F at GTAB points, GPTS=2 points per block.
// grid = 64 blocks x 128 threads
// ---------------------------------------------------------------------------
__global__ void __launch_bounds__(128) k_table(
    const float* __restrict__ Wx,  const float* __restrict__ ax,
    const float* __restrict__ cx,  const float* __restrict__ ac,
    const float* __restrict__ cc,  const float* __restrict__ Wout)
{
    __shared__ __align__(16) float hsh[GPTS][HIDDEN];   // 0.5 KB
    __shared__ __align__(16) float psh[GPTS][NPAIR];    // 5 KB
    __shared__ __align__(16) float sf[GPTS][4][128];    // 4 KB
    __shared__ float phs[GPTS][HIDDEN];                 // 0.5 KB

    const int tid    = threadIdx.x;
    const int wid    = tid >> 5;
    const int lane   = tid & 31;
    const int lane16 = lane & 15;
    const int sel    = lane >> 4;
    const int g0     = blockIdx.x * GPTS;

    // ---- stage 1: h[pt][64], 128 threads = 2 pts x 64 o ----
    {
        const int o  = tid & 63;
        const int pt = tid >> 6;
        float xg = DOM_LO + ((float)(g0 + pt) - 1.5f) * DOM_H;
        float s = 0.f;
        #pragma unroll
        for (int k = 0; k < NBASIS; k++) {
            float tt = tanhf(xg * ax[k] + cx[k]);
            s += tt * Wx[o * NBASIS + k];
        }
        hsh[pt][o] = tanhf(s);
    }
    __syncthreads();

    // ---- stage 2: p[pt][640] ----
    #pragma unroll
    for (int j = 0; j < NPAIR / 128; j++) {
        int pair = j * 128 + tid;
        int i    = pair / NBASIS;
        float a = ac[pair], c = cc[pair];
        #pragma unroll
        for (int pt = 0; pt < GPTS; pt++)
            psh[pt][pair] = tanhf(hsh[pt][i] * a + c);
    }
    __syncthreads();

    // ---- stage 3: per-warp 160-pair reduction ----
    unsigned long long acc0[GPTS], acc1[GPTS];
    #pragma unroll
    for (int pt = 0; pt < GPTS; pt++) { acc0[pt] = 0ull; acc1[pt] = 0ull; }

    const int pair0 = wid * PAIRS_PW;
    const ulonglong2* wb = reinterpret_cast<const ulonglong2*>(g_Wct);

    #pragma unroll 10
    for (int it = 0; it < PAIRS_PW; it += 2) {
        int pair = pair0 + it + sel;
        ulonglong2 w = __ldg(wb + (size_t)pair * 16 + lane16);
        #pragma unroll
        for (int pt = 0; pt < GPTS; pt++) {
            float pj = psh[pt][pair];
            unsigned int pb = __float_as_uint(pj);
            unsigned long long pk;
            asm("mov.b64 %0, {%1, %1};" : "=l"(pk) : "r"(pb));
            asm("fma.rn.f32x2 %0, %1, %2, %0;" : "+l"(acc0[pt]) : "l"(pk), "l"(w.x));
            asm("fma.rn.f32x2 %0, %1, %2, %0;" : "+l"(acc1[pt]) : "l"(pk), "l"(w.y));
        }
    }

    #pragma unroll
    for (int pt = 0; pt < GPTS; pt++) {
        unsigned long long* dst = reinterpret_cast<unsigned long long*>(
            &sf[pt][wid][sel * 64 + 4 * lane16]);
        dst[0] = acc0[pt];
        dst[1] = acc1[pt];
    }
    __syncthreads();

    // ---- combine 8 partials per output, tanh ----
    if (tid < HIDDEN) {
        #pragma unroll
        for (int pt = 0; pt < GPTS; pt++) {
            float tot = 0.f;
            #pragma unroll
            for (int w = 0; w < 4; w++)
                tot += sf[pt][w][tid] + sf[pt][w][tid + 64];
            phs[pt][tid] = tanhf(tot);
        }
    }
    __syncthreads();

    // ---- head: warp 0 ----
    if (tid < 32) {
        float4 wv = __ldg(reinterpret_cast<const float4*>(Wout) + tid);
        #pragma unroll
        for (int pt = 0; pt < GPTS; pt++) {
            float phi0 = phs[pt][2 * tid];
            float phi1 = phs[pt][2 * tid + 1];
            float c0 = phi0 * wv.x + phi1 * wv.z;
            float c1 = phi0 * wv.y + phi1 * wv.w;
            #pragma unroll
            for (int s = 16; s > 0; s >>= 1) {
                c0 += __shfl_xor_sync(0xffffffffu, c0, s);
                c1 += __shfl_xor_sync(0xffffffffu, c1, s);
            }
            if (tid == 0)
                g_table[g0 + pt] = make_float2(c0, c1);
        }
    }
}

// ---------------------------------------------------------------------------
// Kernel B: cubic Lagrange interpolation, table staged in shared
// grid = 32 blocks x 512 threads
// ---------------------------------------------------------------------------
__global__ void __launch_bounds__(512) k_apply(float* __restrict__ out) {
    __shared__ float2 stab[GTAB];
    const int tid = threadIdx.x;
    const int b   = blockIdx.x * 512 + tid;

    float xv = g_xlast[b];          // coalesced
    if (tid < GTAB) stab[tid] = g_table[tid];
    __syncthreads();

    float t = (xv - DOM_LO) * DOM_INVH + 1.5f;
    int i0 = (int)floorf(t);
    i0 = max(1, min(GTAB - 3, i0));
    float u = t - (float)i0;

    float um1 = u - 1.f, um2 = u - 2.f, up1 = u + 1.f;
    float wA = -u * um1 * um2 * (1.f / 6.f);
    float wB =  up1 * um1 * um2 * 0.5f;
    float wC = -up1 * u * um2 * 0.5f;
    float wD =  up1 * u * um1 * (1.f / 6.f);

    float2 fA = stab[i0 - 1];
    float2 fB = stab[i0];
    float2 fC = stab[i0 + 1];
    float2 fD = stab[i0 + 2];

    float o0 = wA * fA.x + wB * fB.x + wC * fC.x + wD * fD.x;
    float o1 = wA * fA.y + wB * fB.y + wC * fC.y + wD * fD.y;
    reinterpret_cast<float2*>(out)[b] = make_float2(o0, o1);
}

// ---------------------------------------------------------------------------
extern "C" void kernel_launch(void* const* d_in, const int* in_sizes, int n_in,
                              void* d_out, int out_size) {
    const float* x    = (const float*)d_in[0];
    const float* Wx   = (const float*)d_in[1];
    const float* ax   = (const float*)d_in[2];
    const float* cx   = (const float*)d_in[3];
    // d_in[4..6] = Wh, ah, ch -- mathematically unused by the reference
    const float* Wc   = (const float*)d_in[7];
    const float* ac   = (const float*)d_in[8];
    const float* cc   = (const float*)d_in[9];
    const float* Wout = (const float*)d_in[10];

    k_pre  <<<TRBLK + XBLK, 256>>>(x, Wc);
    k_table<<<ABLK, 128>>>(Wx, ax, cx, ac, cc, Wout);
    k_apply<<<BATCH / 512, 512>>>((float*)d_out);
}

// round 6
// speedup vs baseline: 1.2574x; 1.2574x over previous
#include <cuda_runtime.h>
#include <math.h>

#define HIDDEN   64
#define NBASIS   10
#define SEQ      96
#define BATCH    16384
#define NPAIR    (HIDDEN * NBASIS)     // 640
#define GTAB     128
#define NBLK     64                    // single wave on 148 SMs -> safe grid barrier
#define NTHR     256
#define GPTS     (GTAB / NBLK)         // 2 grid points per block

#define DOM_LO   (-6.0f)
#define DOM_H    (12.0f / (float)(GTAB - 4))
#define DOM_INVH ((float)(GTAB - 4) / 12.0f)

__device__ float2 g_table[GTAB];
__device__ unsigned int g_bar = 0;     // monotonic ticket barrier (replay-safe)

// ---------------------------------------------------------------------------
// Single fused kernel: phase 1 builds the 128-point table (one block -> 2 pts),
// grid barrier, phase 2 interpolates all 16384 batch elements (1 per thread).
// ---------------------------------------------------------------------------
__global__ void __launch_bounds__(NTHR) k_fused(
    const float* __restrict__ x,
    const float* __restrict__ Wx,  const float* __restrict__ ax,
    const float* __restrict__ cx,  const float* __restrict__ Wc,
    const float* __restrict__ ac,  const float* __restrict__ cc,
    const float* __restrict__ Wout, float* __restrict__ out)
{
    __shared__ float hsh[GPTS][HIDDEN];                     // 0.5 KB
    __shared__ __align__(8) float psh[GPTS][NPAIR];         // 5 KB
    __shared__ float sacc[GPTS][2][HIDDEN];                 // 1 KB
    __shared__ float phs[GPTS][HIDDEN];                     // 0.5 KB
    __shared__ float2 stab[GTAB];                           // 1 KB

    const int tid = threadIdx.x;
    const int b   = blockIdx.x * NTHR + tid;                // exactly BATCH
    const int g0  = blockIdx.x * GPTS;

    // ---- issue the apply-phase x load NOW; latency hides under phase 1 ----
    const float xv = __ldg(x + b * SEQ + (SEQ - 1));

    // ================= phase 1: table =================
    // stage 1: h[pt][o], threads 0..127
    if (tid < GPTS * HIDDEN) {
        int pt = tid >> 6, o = tid & 63;
        float xg = DOM_LO + ((float)(g0 + pt) - 1.5f) * DOM_H;
        float s = 0.f;
        #pragma unroll
        for (int k = 0; k < NBASIS; k++) {
            float t = tanhf(xg * ax[k] + cx[k]);
            s += t * Wx[o * NBASIS + k];
        }
        hsh[pt][o] = tanhf(s);
    }
    __syncthreads();

    // stage 2: p[pt][640] = tanh(h[pt][i]*ac + cc), 1280 over 256 threads
    #pragma unroll
    for (int j = 0; j < GPTS * NPAIR / NTHR; j++) {
        int e    = j * NTHR + tid;
        int pt   = e >= NPAIR;
        int pair = e - pt * NPAIR;
        int i    = pair / NBASIS;
        psh[pt][pair] = tanhf(hsh[pt][i] * ac[pair] + cc[pair]);
    }
    __syncthreads();

    // stage 3: thread = (pt, half, o); accumulate 32 i-rows of Wc directly
    {
        const int pt   = tid >> 7;
        const int half = (tid >> 6) & 1;
        const int o    = tid & 63;
        const float2* Wc2 = reinterpret_cast<const float2*>(Wc);
        const float*  pw  = psh[pt];

        float accA = 0.f, accB = 0.f;
        const int ibase = half * 32;
        #pragma unroll 4
        for (int ii = 0; ii < 32; ii++) {
            int i = ibase + ii;
            const float2* wrow = Wc2 + i * (HIDDEN * NBASIS / 2) + o * (NBASIS / 2);
            const float2* prow = reinterpret_cast<const float2*>(pw + i * NBASIS);
            #pragma unroll
            for (int j = 0; j < NBASIS / 2; j++) {
                float2 w = __ldg(wrow + j);
                float2 p = prow[j];                  // LDS.64 broadcast
                accA = fmaf(p.x, w.x, accA);
                accB = fmaf(p.y, w.y, accB);
            }
        }
        sacc[pt][half][o] = accA + accB;
    }
    __syncthreads();

    // stage 4: combine halves, phi = tanh
    if (tid < GPTS * HIDDEN) {
        int pt = tid >> 6, o = tid & 63;
        phs[pt][o] = tanhf(sacc[pt][0][o] + sacc[pt][1][o]);
    }
    __syncthreads();

    // stage 5: head, warp 0 (o = 2*lane, 2*lane+1)
    if (tid < 32) {
        float4 wv = __ldg(reinterpret_cast<const float4*>(Wout) + tid);
        #pragma unroll
        for (int pt = 0; pt < GPTS; pt++) {
            float c0 = phs[pt][2 * tid] * wv.x + phs[pt][2 * tid + 1] * wv.z;
            float c1 = phs[pt][2 * tid] * wv.y + phs[pt][2 * tid + 1] * wv.w;
            #pragma unroll
            for (int s = 16; s > 0; s >>= 1) {
                c0 += __shfl_xor_sync(0xffffffffu, c0, s);
                c1 += __shfl_xor_sync(0xffffffffu, c1, s);
            }
            if (tid == 0)
                g_table[g0 + pt] = make_float2(c0, c1);
        }
    }

    // ================= grid barrier (single wave, replay-safe) =============
    __threadfence();
    __syncthreads();
    if (tid == 0) {
        unsigned int my = atomicAdd(&g_bar, 1u);
        unsigned int target = (my / NBLK + 1u) * NBLK;
        while (*(volatile unsigned int*)&g_bar < target) { }
    }
    __syncthreads();

    // ================= phase 2: interpolate ===============================
    if (tid < GTAB) {
        const float2* gt = g_table;
        float2 v;
        asm volatile("ld.global.cg.v2.f32 {%0, %1}, [%2];"
                     : "=f"(v.x), "=f"(v.y) : "l"(gt + tid));
        stab[tid] = v;
    }
    __syncthreads();

    float t = (xv - DOM_LO) * DOM_INVH + 1.5f;
    int i0 = (int)floorf(t);
    i0 = max(1, min(GTAB - 3, i0));
    float u = t - (float)i0;

    float um1 = u - 1.f, um2 = u - 2.f, up1 = u + 1.f;
    float wA = -u * um1 * um2 * (1.f / 6.f);
    float wB =  up1 * um1 * um2 * 0.5f;
    float wC = -up1 * u * um2 * 0.5f;
    float wD =  up1 * u * um1 * (1.f / 6.f);

    float2 fA = stab[i0 - 1];
    float2 fB = stab[i0];
    float2 fC = stab[i0 + 1];
    float2 fD = stab[i0 + 2];

    float o0 = wA * fA.x + wB * fB.x + wC * fC.x + wD * fD.x;
    float o1 = wA * fA.y + wB * fB.y + wC * fC.y + wD * fD.y;
    reinterpret_cast<float2*>(out)[b] = make_float2(o0, o1);
}

// ---------------------------------------------------------------------------
extern "C" void kernel_launch(void* const* d_in, const int* in_sizes, int n_in,
                              void* d_out, int out_size) {
    const float* x    = (const float*)d_in[0];
    const float* Wx   = (const float*)d_in[1];
    const float* ax   = (const float*)d_in[2];
    const float* cx   = (const float*)d_in[3];
    // d_in[4..6] = Wh, ah, ch -- mathematically unused by the reference
    const float* Wc   = (const float*)d_in[7];
    const float* ac   = (const float*)d_in[8];
    const float* cc   = (const float*)d_in[9];
    const float* Wout = (const float*)d_in[10];

    k_fused<<<NBLK, NTHR>>>(x, Wx, ax, cx, Wc, ac, cc, Wout, (float*)d_out);
}